// round 1
// baseline (speedup 1.0000x reference)
#include <cuda_runtime.h>
#include <math.h>

#define B_    32
#define NWAY  16
#define LQ    64
#define LD    256
#define D_    128
#define NEGV  (-9999.0f)
#define EPSN  1e-12f

#define RS    68          // padded transposed row stride (multiple of 4 for float4)
#define KTILE 64
#define SMEM_BYTES ((2*128*RS + 64 + 16)*4 + 64*4)

__device__ float g_qn[B_*LQ*D_];       // normalized q scratch (1 MB)
__device__ float g_scores[B_*NWAY];    // per-(b,n) scores

// ---------------- Kernel 1: normalize q rows ----------------
__global__ __launch_bounds__(256) void k_norm_q(const float* __restrict__ q) {
    int row  = blockIdx.x * 8 + (threadIdx.x >> 5);
    int lane = threadIdx.x & 31;
    if (row >= B_*LQ) return;
    float4 v = ((const float4*)(q + (size_t)row*D_))[lane];
    float ss = v.x*v.x + v.y*v.y + v.z*v.z + v.w*v.w;
    #pragma unroll
    for (int o = 16; o; o >>= 1) ss += __shfl_xor_sync(0xffffffffu, ss, o);
    float inv = 1.0f / fmaxf(sqrtf(ss), EPSN);
    float4 o4 = make_float4(v.x*inv, v.y*inv, v.z*inv, v.w*inv);
    ((float4*)(g_qn + (size_t)row*D_))[lane] = o4;
}

// ---------------- Kernel 2: MaxSim scores per (b,n) ----------------
// grid = 512 blocks (b*16+n), 256 threads.
// smem: qs_t[128][RS] (dd-major, q index), ds_t[128][RS] (dd-major, k index),
//       scale[64], red[16], maskb[64]
__global__ __launch_bounds__(256) void k_maxsim(const float* __restrict__ d_reps,
                                                const int*   __restrict__ d_mask) {
    extern __shared__ float sm[];
    float* qs    = sm;                 // 128*RS
    float* ds    = sm + 128*RS;        // 128*RS
    float* scale = ds + 128*RS;        // 64
    float* red   = scale + 64;         // 16
    int*   maskb = (int*)(red + 16);   // 64

    const int b   = blockIdx.x >> 4;
    const int n   = blockIdx.x & 15;
    const int tid = threadIdx.x;
    const int wid = tid >> 5, lane = tid & 31;
    const int kg  = tid & 15,  qg  = tid >> 4;   // 16 k-groups x 16 q-groups

    // stage normalized q transposed: qs[dd][r]
    const float* qn = g_qn + (size_t)b*LQ*D_;
    for (int r = wid; r < LQ; r += 8) {
        #pragma unroll
        for (int c = 0; c < 4; c++) {
            int dd = lane + 32*c;
            qs[dd*RS + r] = qn[r*D_ + dd];
        }
    }

    float m[4];
    #pragma unroll
    for (int i = 0; i < 4; i++) m[i] = -INFINITY;

    const float* dbase = d_reps + (size_t)(b*NWAY + n)*LD*D_;
    const int*   mbase = d_mask + (b*NWAY + n)*LD;

    for (int kt = 0; kt < LD/KTILE; kt++) {
        __syncthreads();   // q staged (kt=0) / previous GEMM readers done
        // stage d tile transposed + per-row sumsq
        for (int r = wid; r < KTILE; r += 8) {
            const float* drow = dbase + (size_t)(kt*KTILE + r)*D_;
            float ss = 0.0f;
            #pragma unroll
            for (int c = 0; c < 4; c++) {
                int dd = lane + 32*c;
                float v = drow[dd];
                ds[dd*RS + r] = v;
                ss += v*v;
            }
            #pragma unroll
            for (int o = 16; o; o >>= 1) ss += __shfl_xor_sync(0xffffffffu, ss, o);
            if (lane == 0) {
                scale[r] = 1.0f / fmaxf(sqrtf(ss), EPSN);
                maskb[r] = mbase[kt*KTILE + r];
            }
        }
        __syncthreads();

        // register-tiled GEMM: acc[i][j] = q(qg*4+i) . d(kg*4+j)
        float acc[4][4];
        #pragma unroll
        for (int i = 0; i < 4; i++)
            #pragma unroll
            for (int j = 0; j < 4; j++) acc[i][j] = 0.0f;

        const float* qp = qs + qg*4;
        const float* dp = ds + kg*4;
        #pragma unroll 4
        for (int dd = 0; dd < D_; dd++) {
            float4 a  = *(const float4*)(qp + dd*RS);
            float4 bb = *(const float4*)(dp + dd*RS);
            acc[0][0] += a.x*bb.x; acc[0][1] += a.x*bb.y; acc[0][2] += a.x*bb.z; acc[0][3] += a.x*bb.w;
            acc[1][0] += a.y*bb.x; acc[1][1] += a.y*bb.y; acc[1][2] += a.y*bb.z; acc[1][3] += a.y*bb.w;
            acc[2][0] += a.z*bb.x; acc[2][1] += a.z*bb.y; acc[2][2] += a.z*bb.z; acc[2][3] += a.z*bb.w;
            acc[3][0] += a.w*bb.x; acc[3][1] += a.w*bb.y; acc[3][2] += a.w*bb.z; acc[3][3] += a.w*bb.w;
        }

        #pragma unroll
        for (int j = 0; j < 4; j++) {
            int k = kg*4 + j;
            float sc = scale[k];
            bool  mk = (maskb[k] != 0);
            #pragma unroll
            for (int i = 0; i < 4; i++) {
                float v = mk ? acc[i][j]*sc : NEGV;
                m[i] = fmaxf(m[i], v);
            }
        }
    }

    // max over the 16 k-groups (lanes differing in bits 0..3 share qg)
    #pragma unroll
    for (int o = 1; o < 16; o <<= 1) {
        #pragma unroll
        for (int i = 0; i < 4; i++)
            m[i] = fmaxf(m[i], __shfl_xor_sync(0xffffffffu, m[i], o));
    }
    if (kg == 0) red[qg] = m[0] + m[1] + m[2] + m[3];
    __syncthreads();
    if (tid == 0) {
        float s = 0.0f;
        #pragma unroll
        for (int i = 0; i < 16; i++) s += red[i];
        g_scores[b*NWAY + n] = s;
    }
}

// ---------------- Kernel 3: softmax + KL (batchmean) ----------------
__global__ __launch_bounds__(1024) void k_loss(const float* __restrict__ labels,
                                               float* __restrict__ out) {
    __shared__ float part[32];
    int wid = threadIdx.x >> 5, lane = threadIdx.x & 31;
    int b = wid;               // 32 warps, one per batch row
    int n = lane & 15;         // both 16-lane halves replicate
    float s   = g_scores[b*NWAY + n];
    float lab = labels[b*NWAY + n];
    float mx = s;
    #pragma unroll
    for (int o = 1; o < 16; o <<= 1) mx = fmaxf(mx, __shfl_xor_sync(0xffffffffu, mx, o));
    float e = expf(s - mx);
    float se = e;
    #pragma unroll
    for (int o = 1; o < 16; o <<= 1) se += __shfl_xor_sync(0xffffffffu, se, o);
    float lse = mx + logf(se);
    float t = expf(lab) * (lab - (s - lse));
    #pragma unroll
    for (int o = 1; o < 16; o <<= 1) t += __shfl_xor_sync(0xffffffffu, t, o);
    if (lane == 0) part[wid] = t;
    __syncthreads();
    if (wid == 0) {
        float v = part[lane];
        #pragma unroll
        for (int o = 16; o; o >>= 1) v += __shfl_xor_sync(0xffffffffu, v, o);
        if (lane == 0) out[0] = v / (float)B_;
    }
}

extern "C" void kernel_launch(void* const* d_in, const int* in_sizes, int n_in,
                              void* d_out, int out_size) {
    const float* q_reps = (const float*)d_in[0];
    const float* d_reps = (const float*)d_in[1];
    const int*   d_mask = (const int*)  d_in[2];
    const float* labels = (const float*)d_in[3];

    k_norm_q<<<(B_*LQ)/8, 256>>>(q_reps);

    cudaFuncSetAttribute(k_maxsim, cudaFuncAttributeMaxDynamicSharedMemorySize, SMEM_BYTES);
    k_maxsim<<<B_*NWAY, 256, SMEM_BYTES>>>(d_reps, d_mask);

    k_loss<<<1, 1024>>>(labels, (float*)d_out);
}

// round 3
// speedup vs baseline: 1.4409x; 1.4409x over previous
#include <cuda_runtime.h>
#include <cuda_bf16.h>
#include <math.h>
#include <stdint.h>

#define B_    32
#define NWAY  16
#define LQ    64
#define LD    256
#define D_    128
#define NEGV  (-9999.0f)
#define EPSN  1e-12f

#define SP    68   // padded row stride in 32-bit words (136 bf16); 68 % 32 == 4 -> conflict-free frags

// SMEM word layout
#define W_DHI  0
#define W_DLO  (W_DHI + 128*SP)
#define W_QHI  (W_DLO + 128*SP)
#define W_QLO  (W_QHI + 64*SP)
#define W_S    (W_QLO + 64*SP)
#define W_O    (W_S + 128)
#define W_WMAX (W_O + 128)
#define SMEM_WORDS (W_WMAX + 256)
#define SMEM_BYTES (SMEM_WORDS*4)

__device__ __align__(16) unsigned g_qhi[B_*LQ*(D_/2)];  // bf16x2, row-major [row][64 words]
__device__ __align__(16) unsigned g_qlo[B_*LQ*(D_/2)];
__device__ float g_scores[B_*NWAY];

__device__ __forceinline__ uint32_t pk(__nv_bfloat16 a, __nv_bfloat16 b){
    __nv_bfloat162 t = __halves2bfloat162(a, b);   // low = a, high = b
    return *reinterpret_cast<uint32_t*>(&t);
}

__device__ __forceinline__ void mma16816(float* c, const uint32_t* a,
                                         uint32_t b0, uint32_t b1){
    asm volatile(
        "mma.sync.aligned.m16n8k16.row.col.f32.bf16.bf16.f32 "
        "{%0,%1,%2,%3}, {%4,%5,%6,%7}, {%8,%9}, {%0,%1,%2,%3};"
        : "+f"(c[0]), "+f"(c[1]), "+f"(c[2]), "+f"(c[3])
        : "r"(a[0]), "r"(a[1]), "r"(a[2]), "r"(a[3]), "r"(b0), "r"(b1));
}

// ---------------- Kernel 1: normalize q + bf16 hi/lo split ----------------
__global__ __launch_bounds__(256) void k_norm_q(const float* __restrict__ q){
    int row  = blockIdx.x * 8 + (threadIdx.x >> 5);
    int lane = threadIdx.x & 31;
    float4 v = ((const float4*)(q + (size_t)row*D_))[lane];
    float ss = v.x*v.x + v.y*v.y + v.z*v.z + v.w*v.w;
    #pragma unroll
    for (int o = 16; o; o >>= 1) ss += __shfl_xor_sync(0xffffffffu, ss, o);
    float inv = 1.0f / fmaxf(sqrtf(ss), EPSN);
    float x0 = v.x*inv, x1 = v.y*inv, x2 = v.z*inv, x3 = v.w*inv;
    __nv_bfloat16 h0 = __float2bfloat16_rn(x0), h1 = __float2bfloat16_rn(x1);
    __nv_bfloat16 h2 = __float2bfloat16_rn(x2), h3 = __float2bfloat16_rn(x3);
    float l0 = x0 - __bfloat162float(h0), l1 = x1 - __bfloat162float(h1);
    float l2 = x2 - __bfloat162float(h2), l3 = x3 - __bfloat162float(h3);
    ((uint2*)(g_qhi + (size_t)row*64))[lane] = make_uint2(pk(h0,h1), pk(h2,h3));
    ((uint2*)(g_qlo + (size_t)row*64))[lane] =
        make_uint2(pk(__float2bfloat16_rn(l0), __float2bfloat16_rn(l1)),
                   pk(__float2bfloat16_rn(l2), __float2bfloat16_rn(l3)));
}

// ---------------- Kernel 2: MaxSim via mma.sync bf16 (grid 512, 128 thr) ----------------
__global__ void __launch_bounds__(128) k_maxsim(const float* __restrict__ d_reps,
                                               const int*   __restrict__ d_mask){
    extern __shared__ unsigned sm[];
    unsigned* dhi  = sm + W_DHI;
    unsigned* dlo  = sm + W_DLO;
    unsigned* qhi  = sm + W_QHI;
    unsigned* qlo  = sm + W_QLO;
    float*    sarr = (float*)(sm + W_S);
    float*    oarr = (float*)(sm + W_O);
    float*    wmax = (float*)(sm + W_WMAX);

    const int tid = threadIdx.x, wid = tid >> 5, lane = tid & 31;
    const int g = lane >> 2, t4 = lane & 3;
    const int b = blockIdx.x >> 4, n = blockIdx.x & 15;

    // ---- stage q hi/lo: rows = q index (64), padded stride SP ----
    {
        int r = tid >> 1, half = tid & 1;
        const uint4* gh = (const uint4*)g_qhi + (size_t)(b*LQ + r)*16 + half*8;
        const uint4* gl = (const uint4*)g_qlo + (size_t)(b*LQ + r)*16 + half*8;
        int wbase = r*SP + half*32;
        #pragma unroll
        for (int j = 0; j < 8; j++){
            *(uint4*)(qhi + wbase + 4*j) = gh[j];
            *(uint4*)(qlo + wbase + 4*j) = gl[j];
        }
    }

    const float* dbase = d_reps + (size_t)(b*NWAY + n) * LD * D_;
    const int*   mbase = d_mask + (b*NWAY + n) * LD;

    float colmax[16];
    #pragma unroll
    for (int i = 0; i < 16; i++) colmax[i] = -INFINITY;

    for (int kt = 0; kt < 2; kt++){
        __syncthreads();
        // ---- stage d tile [128 x 128] fp32 -> bf16 hi/lo + per-row norm/mask ----
        for (int it = 0; it < 32; it++){
            int row = wid*32 + it;
            float4 v = ((const float4*)(dbase + (size_t)(kt*128 + row) * D_))[lane];
            float ss = v.x*v.x + v.y*v.y + v.z*v.z + v.w*v.w;
            #pragma unroll
            for (int o = 16; o; o >>= 1) ss += __shfl_xor_sync(0xffffffffu, ss, o);
            __nv_bfloat16 h0 = __float2bfloat16_rn(v.x), h1 = __float2bfloat16_rn(v.y);
            __nv_bfloat16 h2 = __float2bfloat16_rn(v.z), h3 = __float2bfloat16_rn(v.w);
            float l0 = v.x - __bfloat162float(h0), l1 = v.y - __bfloat162float(h1);
            float l2 = v.z - __bfloat162float(h2), l3 = v.w - __bfloat162float(h3);
            int w = row*SP + 2*lane;
            *(uint2*)(dhi + w) = make_uint2(pk(h0,h1), pk(h2,h3));
            *(uint2*)(dlo + w) =
                make_uint2(pk(__float2bfloat16_rn(l0), __float2bfloat16_rn(l1)),
                           pk(__float2bfloat16_rn(l2), __float2bfloat16_rn(l3)));
            if (lane == 0){
                int mk = mbase[kt*128 + row];
                float inv = 1.0f / fmaxf(sqrtf(ss), EPSN);
                sarr[row] = mk ? inv : 0.0f;
                oarr[row] = mk ? 0.0f : NEGV;
            }
        }
        __syncthreads();

        float C[2][8][4];
        #pragma unroll
        for (int mt = 0; mt < 2; mt++)
            #pragma unroll
            for (int jn = 0; jn < 8; jn++)
                #pragma unroll
                for (int c = 0; c < 4; c++) C[mt][jn][c] = 0.0f;

        #pragma unroll
        for (int ks = 0; ks < 8; ks++){
            uint32_t Ah[2][4], Al[2][4];
            #pragma unroll
            for (int mt = 0; mt < 2; mt++){
                int r0 = (wid*32 + mt*16 + g)*SP + ks*8 + t4;
                Ah[mt][0] = dhi[r0];        Ah[mt][1] = dhi[r0 + 8*SP];
                Ah[mt][2] = dhi[r0 + 4];    Ah[mt][3] = dhi[r0 + 8*SP + 4];
                Al[mt][0] = dlo[r0];        Al[mt][1] = dlo[r0 + 8*SP];
                Al[mt][2] = dlo[r0 + 4];    Al[mt][3] = dlo[r0 + 8*SP + 4];
            }
            #pragma unroll
            for (int jn = 0; jn < 8; jn++){
                int qb = (8*jn + g)*SP + ks*8 + t4;
                uint32_t bh0 = qhi[qb], bh1 = qhi[qb + 4];
                uint32_t bl0 = qlo[qb], bl1 = qlo[qb + 4];
                #pragma unroll
                for (int mt = 0; mt < 2; mt++){
                    mma16816(C[mt][jn], Ah[mt], bh0, bh1);   // hi*hi
                    mma16816(C[mt][jn], Ah[mt], bl0, bl1);   // hi(d)*lo(q)
                    mma16816(C[mt][jn], Al[mt], bh0, bh1);   // lo(d)*hi(q)
                }
            }
        }

        // ---- fold masked+scaled values into per-q col maxes ----
        #pragma unroll
        for (int mt = 0; mt < 2; mt++){
            int r0 = wid*32 + mt*16 + g, r1 = r0 + 8;
            float s0 = sarr[r0], o0 = oarr[r0];
            float s1 = sarr[r1], o1 = oarr[r1];
            #pragma unroll
            for (int jn = 0; jn < 8; jn++){
                colmax[2*jn]   = fmaxf(colmax[2*jn],   fmaf(C[mt][jn][0], s0, o0));
                colmax[2*jn+1] = fmaxf(colmax[2*jn+1], fmaf(C[mt][jn][1], s0, o0));
                colmax[2*jn]   = fmaxf(colmax[2*jn],   fmaf(C[mt][jn][2], s1, o1));
                colmax[2*jn+1] = fmaxf(colmax[2*jn+1], fmaf(C[mt][jn][3], s1, o1));
            }
        }
    }

    // ---- reduce col maxes across lanes sharing the same column (vary g) ----
    #pragma unroll
    for (int i = 0; i < 16; i++){
        #pragma unroll
        for (int o = 4; o < 32; o <<= 1)
            colmax[i] = fmaxf(colmax[i], __shfl_xor_sync(0xffffffffu, colmax[i], o));
    }
    if (lane < 4){
        #pragma unroll
        for (int jn = 0; jn < 8; jn++){
            wmax[wid*64 + 8*jn + 2*lane]     = colmax[2*jn];
            wmax[wid*64 + 8*jn + 2*lane + 1] = colmax[2*jn+1];
        }
    }
    __syncthreads();
    if (wid == 0){
        float a = fmaxf(fmaxf(wmax[lane],      wmax[64+lane]),
                        fmaxf(wmax[128+lane],  wmax[192+lane]));
        float c = fmaxf(fmaxf(wmax[32+lane],   wmax[96+lane]),
                        fmaxf(wmax[160+lane],  wmax[224+lane]));
        float s = a + c;
        #pragma unroll
        for (int o = 16; o; o >>= 1) s += __shfl_xor_sync(0xffffffffu, s, o);
        if (lane == 0) g_scores[b*NWAY + n] = s;
    }
}

// ---------------- Kernel 3: softmax + KL (batchmean) ----------------
__global__ __launch_bounds__(1024) void k_loss(const float* __restrict__ labels,
                                               float* __restrict__ out){
    __shared__ float part[32];
    int wid = threadIdx.x >> 5, lane = threadIdx.x & 31;
    int b = wid;
    int n = lane & 15;
    float s   = g_scores[b*NWAY + n];
    float lab = labels[b*NWAY + n];
    float mx = s;
    #pragma unroll
    for (int o = 1; o < 16; o <<= 1) mx = fmaxf(mx, __shfl_xor_sync(0xffffffffu, mx, o));
    float e = expf(s - mx);
    float se = e;
    #pragma unroll
    for (int o = 1; o < 16; o <<= 1) se += __shfl_xor_sync(0xffffffffu, se, o);
    float lse = mx + logf(se);
    float t = expf(lab) * (lab - (s - lse));
    #pragma unroll
    for (int o = 1; o < 16; o <<= 1) t += __shfl_xor_sync(0xffffffffu, t, o);
    if (lane == 0) part[wid] = t;
    __syncthreads();
    if (wid == 0){
        float v = part[lane];
        #pragma unroll
        for (int o = 16; o; o >>= 1) v += __shfl_xor_sync(0xffffffffu, v, o);
        if (lane == 0) out[0] = v / (float)B_;
    }
}

extern "C" void kernel_launch(void* const* d_in, const int* in_sizes, int n_in,
                              void* d_out, int out_size){
    const float* q_reps = (const float*)d_in[0];
    const float* d_reps = (const float*)d_in[1];
    const int*   d_mask = (const int*)  d_in[2];
    const float* labels = (const float*)d_in[3];

    k_norm_q<<<(B_*LQ)/8, 256>>>(q_reps);

    cudaFuncSetAttribute(k_maxsim, cudaFuncAttributeMaxDynamicSharedMemorySize, SMEM_BYTES);
    k_maxsim<<<B_*NWAY, 128, SMEM_BYTES>>>(d_reps, d_mask);

    k_loss<<<1, 1024>>>(labels, (float*)d_out);
}

// round 4
// speedup vs baseline: 3.2353x; 2.2454x over previous
#include <cuda_runtime.h>
#include <cuda_fp16.h>
#include <math.h>
#include <stdint.h>

#define B_    32
#define NWAY  16
#define LQ    64
#define LD    256
#define D_    128
#define NEGV  (-9999.0f)
#define EPSN  1e-12f

#define SP    68   // padded row stride in 32-bit words; 68 % 32 == 4 -> conflict-free frags

// ---- SMEM word layout ----
#define W_QHI  0
#define W_QLO  (W_QHI + LQ*SP)          // 4352
#define W_DW   (W_QLO + LQ*SP)          // 8704   8 warps x 16 rows x SP
#define W_IDX  (W_DW + 8*16*SP)         // 17408
#define W_SC   (W_IDX + 256)
#define W_OF   (W_SC + 128)
#define W_WMAX (W_OF + 128)             // 8*64
#define W_COLV (W_WMAX + 512)           // 64
#define W_MISC (W_COLV + 64)            // [0]=cnt [1]=lastflag [2..9]=warp bases [16..47]=loss partials
#define SMEM_WORDS (W_MISC + 48)
#define SMEM_BYTES (SMEM_WORDS*4)

__device__ float g_scores[B_*NWAY];
__device__ int   g_done = 0;

__device__ __forceinline__ uint32_t pkh(__half a, __half b){
    __half2 t = __halves2half2(a, b);
    return *reinterpret_cast<uint32_t*>(&t);
}

__device__ __forceinline__ void mma16816(float* c, uint32_t a0, uint32_t a1,
                                         uint32_t a2, uint32_t a3,
                                         uint32_t b0, uint32_t b1){
    asm volatile(
        "mma.sync.aligned.m16n8k16.row.col.f32.f16.f16.f32 "
        "{%0,%1,%2,%3}, {%4,%5,%6,%7}, {%8,%9}, {%0,%1,%2,%3};"
        : "+f"(c[0]), "+f"(c[1]), "+f"(c[2]), "+f"(c[3])
        : "r"(a0), "r"(a1), "r"(a2), "r"(a3), "r"(b0), "r"(b1));
}

// ================= single fused kernel: grid 512, 256 threads =================
__global__ void __launch_bounds__(256) k_fused(const float* __restrict__ q_reps,
                                               const float* __restrict__ d_reps,
                                               const int*   __restrict__ d_mask,
                                               const float* __restrict__ labels,
                                               float* __restrict__ out){
    extern __shared__ unsigned sm[];
    unsigned* qhi  = sm + W_QHI;
    unsigned* qlo  = sm + W_QLO;
    int*      sidx = (int*)(sm + W_IDX);
    float*    ssc  = (float*)(sm + W_SC);
    float*    sof  = (float*)(sm + W_OF);
    float*    wmax = (float*)(sm + W_WMAX);
    float*    colv = (float*)(sm + W_COLV);
    int*      misc = (int*)(sm + W_MISC);
    float*    lpart= (float*)(sm + W_MISC + 16);

    const int tid = threadIdx.x, w = tid >> 5, lane = tid & 31;
    const int g = lane >> 2, t4 = lane & 3;
    const int b = blockIdx.x >> 4, n = blockIdx.x & 15;

    if (tid == 0) misc[0] = 0;
    __syncthreads();

    // ---- mask compaction (ballot) ----
    const int* mbase = d_mask + (b*NWAY + n) * LD;
    {
        int mk = mbase[tid];                       // 256 threads == LD rows
        unsigned bits = __ballot_sync(0xffffffffu, mk);
        if (lane == 0) misc[2 + w] = atomicAdd(&misc[0], __popc(bits));
        __syncwarp();
        int pos = misc[2 + w] + __popc(bits & ((1u << lane) - 1u));
        if (mk) sidx[pos] = tid;
    }

    // ---- fused q normalize + fp16 hi/lo staging (8 rows per warp) ----
    {
        const float* qb = q_reps + (size_t)b * LQ * D_;
        #pragma unroll
        for (int i = 0; i < 8; i++){
            int r = w*8 + i;
            float4 v = ((const float4*)(qb + (size_t)r * D_))[lane];
            float ss = v.x*v.x + v.y*v.y + v.z*v.z + v.w*v.w;
            #pragma unroll
            for (int o = 16; o; o >>= 1) ss += __shfl_xor_sync(0xffffffffu, ss, o);
            float inv = 1.0f / fmaxf(sqrtf(ss), EPSN);
            float x0 = v.x*inv, x1 = v.y*inv, x2 = v.z*inv, x3 = v.w*inv;
            __half h0 = __float2half_rn(x0), h1 = __float2half_rn(x1);
            __half h2 = __float2half_rn(x2), h3 = __float2half_rn(x3);
            float l0 = x0 - __half2float(h0), l1 = x1 - __half2float(h1);
            float l2 = x2 - __half2float(h2), l3 = x3 - __half2float(h3);
            *(uint2*)(qhi + r*SP + 2*lane) = make_uint2(pkh(h0,h1), pkh(h2,h3));
            *(uint2*)(qlo + r*SP + 2*lane) =
                make_uint2(pkh(__float2half_rn(l0), __float2half_rn(l1)),
                           pkh(__float2half_rn(l2), __float2half_rn(l3)));
        }
    }
    __syncthreads();
    const int M_act = misc[0];
    const int nchunk = (M_act + 15) >> 4;

    float colmax[16];
    #pragma unroll
    for (int i = 0; i < 16; i++) colmax[i] = NEGV;

    const float* dbase = d_reps + (size_t)(b*NWAY + n) * LD * D_;
    unsigned* dw = sm + W_DW + w*16*SP;

    // ---- per-warp streaming: stage 16 rows -> mma -> fold ----
    for (int c = w; c < nchunk; c += 8){
        int j0 = c*16;
        __syncwarp();
        #pragma unroll
        for (int ib = 0; ib < 4; ib++){
            float4 vv[4];
            #pragma unroll
            for (int u = 0; u < 4; u++){
                int j = j0 + ib*4 + u;
                if (j < M_act){
                    int orig = sidx[j];
                    vv[u] = ((const float4*)(dbase + (size_t)orig * D_))[lane];
                } else {
                    vv[u] = make_float4(0.f, 0.f, 0.f, 0.f);
                }
            }
            #pragma unroll
            for (int u = 0; u < 4; u++){
                int i = ib*4 + u;
                float4 v = vv[u];
                float ss = v.x*v.x + v.y*v.y + v.z*v.z + v.w*v.w;
                #pragma unroll
                for (int o = 16; o; o >>= 1) ss += __shfl_xor_sync(0xffffffffu, ss, o);
                __half h0 = __float2half_rn(v.x), h1 = __float2half_rn(v.y);
                __half h2 = __float2half_rn(v.z), h3 = __float2half_rn(v.w);
                *(uint2*)(dw + i*SP + 2*lane) = make_uint2(pkh(h0,h1), pkh(h2,h3));
                if (lane == 0){
                    bool val = (j0 + i) < M_act;
                    ssc[w*16 + i] = val ? 1.0f / fmaxf(sqrtf(ss), EPSN) : 0.0f;
                    sof[w*16 + i] = val ? 0.0f : NEGV;
                }
            }
        }
        __syncwarp();

        float C[8][4];
        #pragma unroll
        for (int jn = 0; jn < 8; jn++)
            #pragma unroll
            for (int k = 0; k < 4; k++) C[jn][k] = 0.0f;

        #pragma unroll
        for (int ks = 0; ks < 8; ks++){
            int ab = g*SP + ks*8 + t4;
            uint32_t A0 = dw[ab],     A1 = dw[ab + 8*SP];
            uint32_t A2 = dw[ab + 4], A3 = dw[ab + 8*SP + 4];
            #pragma unroll
            for (int jn = 0; jn < 8; jn++){
                int qb = (jn*8 + g)*SP + ks*8 + t4;
                uint32_t bh0 = qhi[qb], bh1 = qhi[qb + 4];
                uint32_t bl0 = qlo[qb], bl1 = qlo[qb + 4];
                mma16816(C[jn], A0, A1, A2, A3, bh0, bh1);   // d_h * q_hi
                mma16816(C[jn], A0, A1, A2, A3, bl0, bl1);   // d_h * q_lo
            }
        }

        float s0 = ssc[w*16 + g],     o0 = sof[w*16 + g];
        float s1 = ssc[w*16 + g + 8], o1 = sof[w*16 + g + 8];
        #pragma unroll
        for (int jn = 0; jn < 8; jn++){
            colmax[2*jn]   = fmaxf(colmax[2*jn],   fmaf(C[jn][0], s0, o0));
            colmax[2*jn+1] = fmaxf(colmax[2*jn+1], fmaf(C[jn][1], s0, o0));
            colmax[2*jn]   = fmaxf(colmax[2*jn],   fmaf(C[jn][2], s1, o1));
            colmax[2*jn+1] = fmaxf(colmax[2*jn+1], fmaf(C[jn][3], s1, o1));
        }
    }

    // ---- reduce col maxes: intra-warp over g, then cross-warp ----
    #pragma unroll
    for (int i = 0; i < 16; i++){
        #pragma unroll
        for (int o = 4; o < 32; o <<= 1)
            colmax[i] = fmaxf(colmax[i], __shfl_xor_sync(0xffffffffu, colmax[i], o));
    }
    if (lane < 4){
        #pragma unroll
        for (int jn = 0; jn < 8; jn++){
            wmax[w*64 + 8*jn + 2*lane]     = colmax[2*jn];
            wmax[w*64 + 8*jn + 2*lane + 1] = colmax[2*jn+1];
        }
    }
    __syncthreads();
    if (tid < 64){
        float m = wmax[tid];
        #pragma unroll
        for (int ww = 1; ww < 8; ww++) m = fmaxf(m, wmax[ww*64 + tid]);
        colv[tid] = m;
    }
    __syncthreads();
    if (w == 0){
        float s = colv[lane] + colv[lane + 32];
        #pragma unroll
        for (int o = 16; o; o >>= 1) s += __shfl_xor_sync(0xffffffffu, s, o);
        if (lane == 0) g_scores[b*NWAY + n] = s;
    }
    __syncthreads();

    // ---- last CTA computes the KL loss ----
    if (tid == 0){
        __threadfence();
        int dcount = atomicAdd(&g_done, 1);
        misc[1] = (dcount == (int)gridDim.x - 1) ? 1 : 0;
    }
    __syncthreads();
    if (misc[1]){
        __threadfence();
        #pragma unroll
        for (int rep = 0; rep < 2; rep++){
            int bb = rep*16 + (tid >> 4);
            int nn = tid & 15;
            float s   = g_scores[bb*NWAY + nn];
            float lab = labels[bb*NWAY + nn];
            float mx = s;
            #pragma unroll
            for (int o = 1; o < 16; o <<= 1) mx = fmaxf(mx, __shfl_xor_sync(0xffffffffu, mx, o));
            float e = expf(s - mx);
            float se = e;
            #pragma unroll
            for (int o = 1; o < 16; o <<= 1) se += __shfl_xor_sync(0xffffffffu, se, o);
            float lse = mx + logf(se);
            float t = expf(lab) * (lab - (s - lse));
            #pragma unroll
            for (int o = 1; o < 16; o <<= 1) t += __shfl_xor_sync(0xffffffffu, t, o);
            if ((lane & 15) == 0) lpart[rep*16 + (tid >> 4)] = t;
        }
        __syncthreads();
        if (tid < 32){
            float v = lpart[tid];
            #pragma unroll
            for (int o = 16; o; o >>= 1) v += __shfl_xor_sync(0xffffffffu, v, o);
            if (tid == 0){
                out[0] = v / (float)B_;
                __threadfence();
                g_done = 0;                      // reset for the next replay
            }
        }
    }
}

extern "C" void kernel_launch(void* const* d_in, const int* in_sizes, int n_in,
                              void* d_out, int out_size){
    const float* q_reps = (const float*)d_in[0];
    const float* d_reps = (const float*)d_in[1];
    const int*   d_mask = (const int*)  d_in[2];
    const float* labels = (const float*)d_in[3];

    cudaFuncSetAttribute(k_fused, cudaFuncAttributeMaxDynamicSharedMemorySize, SMEM_BYTES);
    k_fused<<<B_*NWAY, 256, SMEM_BYTES>>>(q_reps, d_reps, d_mask, labels, (float*)d_out);
}

// round 5
// speedup vs baseline: 3.3620x; 1.0392x over previous
#include <cuda_runtime.h>
#include <cuda_fp16.h>
#include <math.h>
#include <stdint.h>

#define B_    32
#define NWAY  16
#define LQ    64
#define LD    256
#define D_    128
#define NEGV  (-9999.0f)
#define EPSN  1e-12f

#define SP    68   // padded row stride (words); 68 % 32 == 4 -> conflict-free frags

// ---- SMEM word layout. W_U is a union: q staging (prologue) / fp32 stage (mainloop) ----
#define W_U    0
#define W_QHI  (W_U)                    // 64*SP = 4352
#define W_QLO  (W_U + 4352)             // 4352
#define W_F32  (W_U)                    // 2 bufs x 4096 (32 rows x 128 words)
#define W_A16  8704                     // 2 bufs x 2176 (32 rows x SP)
#define W_SIDX 13056                    // 256
#define W_SC   13312                    // [2][32]
#define W_OF   13376                    // [2][32]
#define W_WS   13440                    // 8 warp sums
#define W_MISC 13448                    // [0]=cnt [1]=flag [2..9]=bases [16..47]=lpart
#define SMEM_WORDS (W_MISC + 48)
#define SMEM_BYTES (SMEM_WORDS*4)

__device__ float g_scores[B_*NWAY];
__device__ int   g_done = 0;

__device__ __forceinline__ uint32_t pkh(__half a, __half b){
    __half2 t = __halves2half2(a, b);
    return *reinterpret_cast<uint32_t*>(&t);
}
__device__ __forceinline__ uint32_t s2u(const void* p){
    uint32_t a;
    asm("{ .reg .u64 t; cvta.to.shared.u64 t, %1; cvt.u32.u64 %0, t; }" : "=r"(a) : "l"(p));
    return a;
}
__device__ __forceinline__ void mma16816(float* c, uint32_t a0, uint32_t a1,
                                         uint32_t a2, uint32_t a3,
                                         uint32_t b0, uint32_t b1){
    asm volatile(
        "mma.sync.aligned.m16n8k16.row.col.f32.f16.f16.f32 "
        "{%0,%1,%2,%3}, {%4,%5,%6,%7}, {%8,%9}, {%0,%1,%2,%3};"
        : "+f"(c[0]), "+f"(c[1]), "+f"(c[2]), "+f"(c[3])
        : "r"(a0), "r"(a1), "r"(a2), "r"(a3), "r"(b0), "r"(b1));
}
__device__ __forceinline__ void ldmx4(uint32_t& r0, uint32_t& r1, uint32_t& r2,
                                      uint32_t& r3, uint32_t addr){
    asm volatile("ldmatrix.sync.aligned.m8n8.x4.shared.b16 {%0,%1,%2,%3}, [%4];"
                 : "=r"(r0), "=r"(r1), "=r"(r2), "=r"(r3) : "r"(addr));
}

// ================= fused kernel: grid 512, 256 threads =================
__global__ void __launch_bounds__(256, 3) k_fused(const float* __restrict__ q_reps,
                                                  const float* __restrict__ d_reps,
                                                  const int*   __restrict__ d_mask,
                                                  const float* __restrict__ labels,
                                                  float* __restrict__ out){
    extern __shared__ unsigned sm[];
    unsigned* qhi  = sm + W_QHI;
    unsigned* qlo  = sm + W_QLO;
    int*      sidx = (int*)(sm + W_SIDX);
    float*    ssc  = (float*)(sm + W_SC);
    float*    sof  = (float*)(sm + W_OF);
    float*    ws   = (float*)(sm + W_WS);
    int*      misc = (int*)(sm + W_MISC);
    float*    lpart= (float*)(sm + W_MISC + 16);
    const uint32_t smem32 = s2u(sm);

    const int tid = threadIdx.x, w = tid >> 5, lane = tid & 31;
    const int g = lane >> 2, t4 = lane & 3;
    const int b = blockIdx.x >> 4, n = blockIdx.x & 15;
    const int crow = tid >> 3, cseg = tid & 7;   // cp.async mapping

    if (tid == 0) misc[0] = 0;
    __syncthreads();

    // ---- mask compaction ----
    const int* mbase = d_mask + (b*NWAY + n) * LD;
    {
        int mk = mbase[tid];
        unsigned bits = __ballot_sync(0xffffffffu, mk);
        if (lane == 0) misc[2 + w] = atomicAdd(&misc[0], __popc(bits));
        __syncwarp();
        int pos = misc[2 + w] + __popc(bits & ((1u << lane) - 1u));
        if (mk) sidx[pos] = tid;
    }

    // ---- q normalize + fp16 hi/lo -> smem (own warp rows), then B frags -> regs ----
    {
        const float* qb = q_reps + (size_t)b * LQ * D_;
        #pragma unroll
        for (int i = 0; i < 8; i++){
            int r = w*8 + i;
            float4 v = ((const float4*)(qb + (size_t)r * D_))[lane];
            float ss = v.x*v.x + v.y*v.y + v.z*v.z + v.w*v.w;
            #pragma unroll
            for (int o = 16; o; o >>= 1) ss += __shfl_xor_sync(0xffffffffu, ss, o);
            float inv = 1.0f / fmaxf(sqrtf(ss), EPSN);
            float x0 = v.x*inv, x1 = v.y*inv, x2 = v.z*inv, x3 = v.w*inv;
            __half h0 = __float2half_rn(x0), h1 = __float2half_rn(x1);
            __half h2 = __float2half_rn(x2), h3 = __float2half_rn(x3);
            float l0 = x0 - __half2float(h0), l1 = x1 - __half2float(h1);
            float l2 = x2 - __half2float(h2), l3 = x3 - __half2float(h3);
            *(uint2*)(qhi + r*SP + 2*lane) = make_uint2(pkh(h0,h1), pkh(h2,h3));
            *(uint2*)(qlo + r*SP + 2*lane) =
                make_uint2(pkh(__float2half_rn(l0), __float2half_rn(l1)),
                           pkh(__float2half_rn(l2), __float2half_rn(l3)));
        }
    }
    __syncwarp();
    uint32_t Bh0[8], Bh1[8], Bl0[8], Bl1[8];
    {
        int qr = (w*8 + g)*SP;
        #pragma unroll
        for (int ks = 0; ks < 8; ks++){
            Bh0[ks] = qhi[qr + ks*8 + t4];  Bh1[ks] = qhi[qr + ks*8 + t4 + 4];
            Bl0[ks] = qlo[qr + ks*8 + t4];  Bl1[ks] = qlo[qr + ks*8 + t4 + 4];
        }
    }
    __syncthreads();   // sidx ready, all q reads done -> W_U reusable as fp32 stage

    const int M_act = misc[0];
    const int nchunk = (M_act + 31) >> 5;
    const float* dbase = d_reps + (size_t)(b*NWAY + n) * LD * D_;

    // ---- prefetch chunks 0,1 ----
    #pragma unroll
    for (int c0 = 0; c0 < 2; c0++){
        if (c0 < nchunk){
            int j = c0*32 + crow;
            int orig = sidx[(j < M_act) ? j : 0];
            const char* src = (const char*)(dbase + (size_t)orig * D_);
            uint32_t dst = smem32 + (uint32_t)((W_F32 + (c0&1)*4096 + crow*128)*4);
            #pragma unroll
            for (int it = 0; it < 4; it++){
                uint32_t o = (uint32_t)((cseg + 8*it) * 16);
                asm volatile("cp.async.cg.shared.global [%0], [%1], 16;"
                             :: "r"(dst + o), "l"(src + o) : "memory");
            }
        }
        asm volatile("cp.async.commit_group;" ::: "memory");
    }

    float cm0 = NEGV, cm1 = NEGV;
    const uint32_t afragoff = (uint32_t)((lane & 15)*SP*4 + (lane >> 4)*16);

    for (int c = 0; c < nchunk; c++){
        const int slot = c & 1;
        asm volatile("cp.async.wait_group 1;" ::: "memory");
        __syncthreads();

        // ---- convert 4 rows per warp: fp32 smem -> fp16 A tile + norms ----
        {
            const float* fb = (const float*)(sm + W_F32 + slot*4096);
            unsigned* ab = sm + W_A16 + slot*2176;
            #pragma unroll
            for (int i = 0; i < 4; i++){
                int row = w*4 + i;
                float4 v = *(const float4*)(fb + row*128 + lane*4);
                float ss = v.x*v.x + v.y*v.y + v.z*v.z + v.w*v.w;
                #pragma unroll
                for (int o = 16; o; o >>= 1) ss += __shfl_xor_sync(0xffffffffu, ss, o);
                *(uint2*)(ab + row*SP + 2*lane) =
                    make_uint2(pkh(__float2half_rn(v.x), __float2half_rn(v.y)),
                               pkh(__float2half_rn(v.z), __float2half_rn(v.w)));
                if (lane == 0){
                    bool val = (c*32 + row) < M_act;
                    ssc[slot*32 + row] = val ? 1.0f / fmaxf(sqrtf(ss), EPSN) : 0.0f;
                    sof[slot*32 + row] = val ? 0.0f : NEGV;
                }
            }
        }
        __syncthreads();

        // ---- prefetch chunk c+2 into the buffer just freed ----
        if (c + 2 < nchunk){
            int j = (c+2)*32 + crow;
            int orig = sidx[(j < M_act) ? j : 0];
            const char* src = (const char*)(dbase + (size_t)orig * D_);
            uint32_t dst = smem32 + (uint32_t)((W_F32 + slot*4096 + crow*128)*4);
            #pragma unroll
            for (int it = 0; it < 4; it++){
                uint32_t o = (uint32_t)((cseg + 8*it) * 16);
                asm volatile("cp.async.cg.shared.global [%0], [%1], 16;"
                             :: "r"(dst + o), "l"(src + o) : "memory");
            }
        }
        asm volatile("cp.async.commit_group;" ::: "memory");

        // ---- MMA: each warp does its n8 tile over both m16 tiles ----
        const uint32_t abB = smem32 + (uint32_t)((W_A16 + slot*2176)*4) + afragoff;
        #pragma unroll
        for (int mt = 0; mt < 2; mt++){
            float C[4] = {0.f, 0.f, 0.f, 0.f};
            #pragma unroll
            for (int ks = 0; ks < 8; ks++){
                uint32_t a0, a1, a2, a3;
                ldmx4(a0, a1, a2, a3, abB + (uint32_t)(mt*16*SP*4 + ks*32));
                mma16816(C, a0, a1, a2, a3, Bh0[ks], Bh1[ks]);
                mma16816(C, a0, a1, a2, a3, Bl0[ks], Bl1[ks]);
            }
            float s0 = ssc[slot*32 + mt*16 + g],     o0 = sof[slot*32 + mt*16 + g];
            float s1 = ssc[slot*32 + mt*16 + g + 8], o1 = sof[slot*32 + mt*16 + g + 8];
            cm0 = fmaxf(cm0, fmaf(C[0], s0, o0));
            cm1 = fmaxf(cm1, fmaf(C[1], s0, o0));
            cm0 = fmaxf(cm0, fmaf(C[2], s1, o1));
            cm1 = fmaxf(cm1, fmaf(C[3], s1, o1));
        }
    }

    // ---- reduce: max over g (rows), then sum the warp's 8 q columns ----
    #pragma unroll
    for (int o = 4; o < 32; o <<= 1){
        cm0 = fmaxf(cm0, __shfl_xor_sync(0xffffffffu, cm0, o));
        cm1 = fmaxf(cm1, __shfl_xor_sync(0xffffffffu, cm1, o));
    }
    float s = cm0 + cm1;
    s += __shfl_xor_sync(0xffffffffu, s, 1);
    s += __shfl_xor_sync(0xffffffffu, s, 2);
    if (lane == 0) ws[w] = s;
    __syncthreads();
    if (tid == 0){
        float sc = 0.f;
        #pragma unroll
        for (int i = 0; i < 8; i++) sc += ws[i];
        g_scores[b*NWAY + n] = sc;
    }
    __syncthreads();

    // ---- last CTA computes the KL loss ----
    if (tid == 0){
        __threadfence();
        int dcount = atomicAdd(&g_done, 1);
        misc[1] = (dcount == (int)gridDim.x - 1) ? 1 : 0;
    }
    __syncthreads();
    if (misc[1]){
        __threadfence();
        #pragma unroll
        for (int rep = 0; rep < 2; rep++){
            int bb = rep*16 + (tid >> 4);
            int nn = tid & 15;
            float sv  = g_scores[bb*NWAY + nn];
            float lab = labels[bb*NWAY + nn];
            float mx = sv;
            #pragma unroll
            for (int o = 1; o < 16; o <<= 1) mx = fmaxf(mx, __shfl_xor_sync(0xffffffffu, mx, o));
            float e = expf(sv - mx);
            float se = e;
            #pragma unroll
            for (int o = 1; o < 16; o <<= 1) se += __shfl_xor_sync(0xffffffffu, se, o);
            float lse = mx + logf(se);
            float t = expf(lab) * (lab - (sv - lse));
            #pragma unroll
            for (int o = 1; o < 16; o <<= 1) t += __shfl_xor_sync(0xffffffffu, t, o);
            if ((lane & 15) == 0) lpart[rep*16 + (tid >> 4)] = t;
        }
        __syncthreads();
        if (tid < 32){
            float v = lpart[tid];
            #pragma unroll
            for (int o = 16; o; o >>= 1) v += __shfl_xor_sync(0xffffffffu, v, o);
            if (tid == 0){
                out[0] = v / (float)B_;
                __threadfence();
                g_done = 0;
            }
        }
    }
}

extern "C" void kernel_launch(void* const* d_in, const int* in_sizes, int n_in,
                              void* d_out, int out_size){
    const float* q_reps = (const float*)d_in[0];
    const float* d_reps = (const float*)d_in[1];
    const int*   d_mask = (const int*)  d_in[2];
    const float* labels = (const float*)d_in[3];

    cudaFuncSetAttribute(k_fused, cudaFuncAttributeMaxDynamicSharedMemorySize, SMEM_BYTES);
    k_fused<<<B_*NWAY, 256, SMEM_BYTES>>>(q_reps, d_reps, d_mask, labels, (float*)d_out);
}

// round 6
// speedup vs baseline: 3.4175x; 1.0165x over previous
#include <cuda_runtime.h>
#include <cuda_fp16.h>
#include <math.h>
#include <stdint.h>

#define B_    32
#define NWAY  16
#define LQ    64
#define LD    256
#define D_    128
#define NEGV  (-9999.0f)
#define EPSN  1e-12f

#define SP    68   // padded row stride (words); 68 % 32 == 4 -> conflict-free frags

// ---- SMEM word layout. W_U is a union: q staging (prologue) / fp32 stage (mainloop) ----
#define W_U    0
#define W_QHI  (W_U)                    // 64*SP = 4352
#define W_QLO  (W_U + 4352)             // 4352
#define W_F32  (W_U)                    // 2 bufs x 4096 (32 rows x 128 words)
#define W_A16  8704                     // 2 bufs x 2176 (32 rows x SP)
#define W_SIDX 13056                    // 256
#define W_SC   13312                    // [2][32]
#define W_OF   13376                    // [2][32]
#define W_WS   13440                    // 8 warp sums
#define W_MISC 13448                    // [0]=cnt [1]=flag [2..9]=bases [16..47]=lpart
#define SMEM_WORDS (W_MISC + 48)
#define SMEM_BYTES (SMEM_WORDS*4)

__device__ float g_scores[B_*NWAY];
__device__ int   g_done = 0;

__device__ __forceinline__ uint32_t pkh(__half a, __half b){
    __half2 t = __halves2half2(a, b);
    return *reinterpret_cast<uint32_t*>(&t);
}
__device__ __forceinline__ uint32_t s2u(const void* p){
    uint32_t a;
    asm("{ .reg .u64 t; cvta.to.shared.u64 t, %1; cvt.u32.u64 %0, t; }" : "=r"(a) : "l"(p));
    return a;
}
__device__ __forceinline__ void mma16816(float* c, uint32_t a0, uint32_t a1,
                                         uint32_t a2, uint32_t a3,
                                         uint32_t b0, uint32_t b1){
    asm volatile(
        "mma.sync.aligned.m16n8k16.row.col.f32.f16.f16.f32 "
        "{%0,%1,%2,%3}, {%4,%5,%6,%7}, {%8,%9}, {%0,%1,%2,%3};"
        : "+f"(c[0]), "+f"(c[1]), "+f"(c[2]), "+f"(c[3])
        : "r"(a0), "r"(a1), "r"(a2), "r"(a3), "r"(b0), "r"(b1));
}
__device__ __forceinline__ void ldmx4(uint32_t& r0, uint32_t& r1, uint32_t& r2,
                                      uint32_t& r3, uint32_t addr){
    asm volatile("ldmatrix.sync.aligned.m8n8.x4.shared.b16 {%0,%1,%2,%3}, [%4];"
                 : "=r"(r0), "=r"(r1), "=r"(r2), "=r"(r3) : "r"(addr));
}

// ================= fused kernel: grid 512, 256 threads =================
__global__ void __launch_bounds__(256, 3) k_fused(const float* __restrict__ q_reps,
                                                  const float* __restrict__ d_reps,
                                                  const int*   __restrict__ d_mask,
                                                  const float* __restrict__ labels,
                                                  float* __restrict__ out){
    extern __shared__ unsigned sm[];
    unsigned* qhi  = sm + W_QHI;
    unsigned* qlo  = sm + W_QLO;
    int*      sidx = (int*)(sm + W_SIDX);
    float*    ssc  = (float*)(sm + W_SC);
    float*    sof  = (float*)(sm + W_OF);
    float*    ws   = (float*)(sm + W_WS);
    int*      misc = (int*)(sm + W_MISC);
    float*    lpart= (float*)(sm + W_MISC + 16);
    const uint32_t smem32 = s2u(sm);

    const int tid = threadIdx.x, w = tid >> 5, lane = tid & 31;
    const int g = lane >> 2, t4 = lane & 3;
    const int b = blockIdx.x >> 4, n = blockIdx.x & 15;
    const int crow = tid >> 3, cseg = tid & 7;   // cp.async mapping

    if (tid == 0) misc[0] = 0;
    __syncthreads();

    // ---- mask compaction ----
    const int* mbase = d_mask + (b*NWAY + n) * LD;
    {
        int mk = mbase[tid];
        unsigned bits = __ballot_sync(0xffffffffu, mk);
        if (lane == 0) misc[2 + w] = atomicAdd(&misc[0], __popc(bits));
        __syncwarp();
        int pos = misc[2 + w] + __popc(bits & ((1u << lane) - 1u));
        if (mk) sidx[pos] = tid;
    }

    // ---- q normalize + fp16 hi/lo -> smem (own warp rows), then B frags -> regs ----
    {
        const float* qb = q_reps + (size_t)b * LQ * D_;
        #pragma unroll
        for (int i = 0; i < 8; i++){
            int r = w*8 + i;
            float4 v = ((const float4*)(qb + (size_t)r * D_))[lane];
            float ss = v.x*v.x + v.y*v.y + v.z*v.z + v.w*v.w;
            #pragma unroll
            for (int o = 16; o; o >>= 1) ss += __shfl_xor_sync(0xffffffffu, ss, o);
            float inv = 1.0f / fmaxf(sqrtf(ss), EPSN);
            float x0 = v.x*inv, x1 = v.y*inv, x2 = v.z*inv, x3 = v.w*inv;
            __half h0 = __float2half_rn(x0), h1 = __float2half_rn(x1);
            __half h2 = __float2half_rn(x2), h3 = __float2half_rn(x3);
            float l0 = x0 - __half2float(h0), l1 = x1 - __half2float(h1);
            float l2 = x2 - __half2float(h2), l3 = x3 - __half2float(h3);
            *(uint2*)(qhi + r*SP + 2*lane) = make_uint2(pkh(h0,h1), pkh(h2,h3));
            *(uint2*)(qlo + r*SP + 2*lane) =
                make_uint2(pkh(__float2half_rn(l0), __float2half_rn(l1)),
                           pkh(__float2half_rn(l2), __float2half_rn(l3)));
        }
    }
    __syncwarp();
    uint32_t Bh0[8], Bh1[8], Bl0[8], Bl1[8];
    {
        int qr = (w*8 + g)*SP;
        #pragma unroll
        for (int ks = 0; ks < 8; ks++){
            Bh0[ks] = qhi[qr + ks*8 + t4];  Bh1[ks] = qhi[qr + ks*8 + t4 + 4];
            Bl0[ks] = qlo[qr + ks*8 + t4];  Bl1[ks] = qlo[qr + ks*8 + t4 + 4];
        }
    }
    __syncthreads();   // sidx ready, all q reads done -> W_U reusable as fp32 stage

    const int M_act = misc[0];
    const int nchunk = (M_act + 31) >> 5;
    const float* dbase = d_reps + (size_t)(b*NWAY + n) * LD * D_;

    // ---- prefetch chunks 0,1 ----
    #pragma unroll
    for (int c0 = 0; c0 < 2; c0++){
        if (c0 < nchunk){
            int j = c0*32 + crow;
            int orig = sidx[(j < M_act) ? j : 0];
            const char* src = (const char*)(dbase + (size_t)orig * D_);
            uint32_t dst = smem32 + (uint32_t)((W_F32 + (c0&1)*4096 + crow*128)*4);
            #pragma unroll
            for (int it = 0; it < 4; it++){
                uint32_t o = (uint32_t)((cseg + 8*it) * 16);
                asm volatile("cp.async.cg.shared.global [%0], [%1], 16;"
                             :: "r"(dst + o), "l"(src + o) : "memory");
            }
        }
        asm volatile("cp.async.commit_group;" ::: "memory");
    }

    float cm0 = NEGV, cm1 = NEGV;
    const uint32_t afragoff = (uint32_t)((lane & 15)*SP*4 + (lane >> 4)*16);

    for (int c = 0; c < nchunk; c++){
        const int slot = c & 1;
        asm volatile("cp.async.wait_group 1;" ::: "memory");
        __syncthreads();

        // ---- convert 4 rows per warp: fp32 smem -> fp16 A tile + norms ----
        {
            const float* fb = (const float*)(sm + W_F32 + slot*4096);
            unsigned* ab = sm + W_A16 + slot*2176;
            #pragma unroll
            for (int i = 0; i < 4; i++){
                int row = w*4 + i;
                float4 v = *(const float4*)(fb + row*128 + lane*4);
                float ss = v.x*v.x + v.y*v.y + v.z*v.z + v.w*v.w;
                #pragma unroll
                for (int o = 16; o; o >>= 1) ss += __shfl_xor_sync(0xffffffffu, ss, o);
                *(uint2*)(ab + row*SP + 2*lane) =
                    make_uint2(pkh(__float2half_rn(v.x), __float2half_rn(v.y)),
                               pkh(__float2half_rn(v.z), __float2half_rn(v.w)));
                if (lane == 0){
                    bool val = (c*32 + row) < M_act;
                    ssc[slot*32 + row] = val ? 1.0f / fmaxf(sqrtf(ss), EPSN) : 0.0f;
                    sof[slot*32 + row] = val ? 0.0f : NEGV;
                }
            }
        }
        __syncthreads();

        // ---- prefetch chunk c+2 into the buffer just freed ----
        if (c + 2 < nchunk){
            int j = (c+2)*32 + crow;
            int orig = sidx[(j < M_act) ? j : 0];
            const char* src = (const char*)(dbase + (size_t)orig * D_);
            uint32_t dst = smem32 + (uint32_t)((W_F32 + slot*4096 + crow*128)*4);
            #pragma unroll
            for (int it = 0; it < 4; it++){
                uint32_t o = (uint32_t)((cseg + 8*it) * 16);
                asm volatile("cp.async.cg.shared.global [%0], [%1], 16;"
                             :: "r"(dst + o), "l"(src + o) : "memory");
            }
        }
        asm volatile("cp.async.commit_group;" ::: "memory");

        // ---- MMA: each warp does its n8 tile over both m16 tiles ----
        const uint32_t abB = smem32 + (uint32_t)((W_A16 + slot*2176)*4) + afragoff;
        #pragma unroll
        for (int mt = 0; mt < 2; mt++){
            float C[4] = {0.f, 0.f, 0.f, 0.f};
            #pragma unroll
            for (int ks = 0; ks < 8; ks++){
                uint32_t a0, a1, a2, a3;
                ldmx4(a0, a1, a2, a3, abB + (uint32_t)(mt*16*SP*4 + ks*32));
                mma16816(C, a0, a1, a2, a3, Bh0[ks], Bh1[ks]);
                mma16816(C, a0, a1, a2, a3, Bl0[ks], Bl1[ks]);
            }
            float s0 = ssc[slot*32 + mt*16 + g],     o0 = sof[slot*32 + mt*16 + g];
            float s1 = ssc[slot*32 + mt*16 + g + 8], o1 = sof[slot*32 + mt*16 + g + 8];
            cm0 = fmaxf(cm0, fmaf(C[0], s0, o0));
            cm1 = fmaxf(cm1, fmaf(C[1], s0, o0));
            cm0 = fmaxf(cm0, fmaf(C[2], s1, o1));
            cm1 = fmaxf(cm1, fmaf(C[3], s1, o1));
        }
    }

    // ---- reduce: max over g (rows), then sum the warp's 8 q columns ----
    #pragma unroll
    for (int o = 4; o < 32; o <<= 1){
        cm0 = fmaxf(cm0, __shfl_xor_sync(0xffffffffu, cm0, o));
        cm1 = fmaxf(cm1, __shfl_xor_sync(0xffffffffu, cm1, o));
    }
    float s = cm0 + cm1;
    s += __shfl_xor_sync(0xffffffffu, s, 1);
    s += __shfl_xor_sync(0xffffffffu, s, 2);
    if (lane == 0) ws[w] = s;
    __syncthreads();
    if (tid == 0){
        float sc = 0.f;
        #pragma unroll
        for (int i = 0; i < 8; i++) sc += ws[i];
        g_scores[b*NWAY + n] = sc;
    }
    __syncthreads();

    // ---- last CTA computes the KL loss ----
    if (tid == 0){
        __threadfence();
        int dcount = atomicAdd(&g_done, 1);
        misc[1] = (dcount == (int)gridDim.x - 1) ? 1 : 0;
    }
    __syncthreads();
    if (misc[1]){
        __threadfence();
        #pragma unroll
        for (int rep = 0; rep < 2; rep++){
            int bb = rep*16 + (tid >> 4);
            int nn = tid & 15;
            float sv  = g_scores[bb*NWAY + nn];
            float lab = labels[bb*NWAY + nn];
            float mx = sv;
            #pragma unroll
            for (int o = 1; o < 16; o <<= 1) mx = fmaxf(mx, __shfl_xor_sync(0xffffffffu, mx, o));
            float e = expf(sv - mx);
            float se = e;
            #pragma unroll
            for (int o = 1; o < 16; o <<= 1) se += __shfl_xor_sync(0xffffffffu, se, o);
            float lse = mx + logf(se);
            float t = expf(lab) * (lab - (sv - lse));
            #pragma unroll
            for (int o = 1; o < 16; o <<= 1) t += __shfl_xor_sync(0xffffffffu, t, o);
            if ((lane & 15) == 0) lpart[rep*16 + (tid >> 4)] = t;
        }
        __syncthreads();
        if (tid < 32){
            float v = lpart[tid];
            #pragma unroll
            for (int o = 16; o; o >>= 1) v += __shfl_xor_sync(0xffffffffu, v, o);
            if (tid == 0){
                out[0] = v / (float)B_;
                __threadfence();
                g_done = 0;
            }
        }
    }
}

extern "C" void kernel_launch(void* const* d_in, const int* in_sizes, int n_in,
                              void* d_out, int out_size){
    const float* q_reps = (const float*)d_in[0];
    const float* d_reps = (const float*)d_in[1];
    const int*   d_mask = (const int*)  d_in[2];
    const float* labels = (const float*)d_in[3];

    cudaFuncSetAttribute(k_fused, cudaFuncAttributeMaxDynamicSharedMemorySize, SMEM_BYTES);
    k_fused<<<B_*NWAY, 256, SMEM_BYTES>>>(q_reps, d_reps, d_mask, labels, (float*)d_out);
}

// round 7
// speedup vs baseline: 3.4275x; 1.0029x over previous
#include <cuda_runtime.h>
#include <cuda_fp16.h>
#include <math.h>
#include <stdint.h>

#define B_    32
#define NWAY  16
#define LQ    64
#define LD    256
#define D_    128
#define NEGV  (-9999.0f)
#define EPSN  1e-12f

#define SP    68   // padded row stride (words); 68 % 32 == 4 -> conflict-free frags

// ---- SMEM word layout. W_U is a union: q staging (prologue) / fp32 stage (mainloop) ----
#define W_U    0
#define W_QHI  (W_U)                    // 64*SP = 4352
#define W_QLO  (W_U + 4352)             // 4352
#define W_F32  (W_U)                    // 2 bufs x 4096 (32 rows x 128 words)
#define W_A16  8704                     // 2 bufs x 2176 (32 rows x SP)
#define W_SIDX 13056                    // 256
#define W_SC   13312                    // [2][32]
#define W_OF   13376                    // [2][32]
#define W_WS   13440                    // 8 warp sums
#define W_MISC 13448                    // [0]=cnt [1]=flag [2..9]=bases [16..47]=lpart
#define SMEM_WORDS (W_MISC + 48)
#define SMEM_BYTES (SMEM_WORDS*4)

__device__ float g_scores[B_*NWAY];
__device__ int   g_done = 0;

__device__ __forceinline__ uint32_t pkh(__half a, __half b){
    __half2 t = __halves2half2(a, b);
    return *reinterpret_cast<uint32_t*>(&t);
}
__device__ __forceinline__ uint32_t s2u(const void* p){
    uint32_t a;
    asm("{ .reg .u64 t; cvta.to.shared.u64 t, %1; cvt.u32.u64 %0, t; }" : "=r"(a) : "l"(p));
    return a;
}
__device__ __forceinline__ void mma16816(float* c, uint32_t a0, uint32_t a1,
                                         uint32_t a2, uint32_t a3,
                                         uint32_t b0, uint32_t b1){
    asm volatile(
        "mma.sync.aligned.m16n8k16.row.col.f32.f16.f16.f32 "
        "{%0,%1,%2,%3}, {%4,%5,%6,%7}, {%8,%9}, {%0,%1,%2,%3};"
        : "+f"(c[0]), "+f"(c[1]), "+f"(c[2]), "+f"(c[3])
        : "r"(a0), "r"(a1), "r"(a2), "r"(a3), "r"(b0), "r"(b1));
}
__device__ __forceinline__ void ldmx4(uint32_t& r0, uint32_t& r1, uint32_t& r2,
                                      uint32_t& r3, uint32_t addr){
    asm volatile("ldmatrix.sync.aligned.m8n8.x4.shared.b16 {%0,%1,%2,%3}, [%4];"
                 : "=r"(r0), "=r"(r1), "=r"(r2), "=r"(r3) : "r"(addr));
}

// ================= fused kernel: grid 512, 256 threads =================
__global__ void __launch_bounds__(256, 3) k_fused(const float* __restrict__ q_reps,
                                                  const float* __restrict__ d_reps,
                                                  const int*   __restrict__ d_mask,
                                                  const float* __restrict__ labels,
                                                  float* __restrict__ out){
    extern __shared__ unsigned sm[];
    unsigned* qhi  = sm + W_QHI;
    unsigned* qlo  = sm + W_QLO;
    int*      sidx = (int*)(sm + W_SIDX);
    float*    ssc  = (float*)(sm + W_SC);
    float*    sof  = (float*)(sm + W_OF);
    float*    ws   = (float*)(sm + W_WS);
    int*      misc = (int*)(sm + W_MISC);
    float*    lpart= (float*)(sm + W_MISC + 16);
    const uint32_t smem32 = s2u(sm);

    const int tid = threadIdx.x, w = tid >> 5, lane = tid & 31;
    const int g = lane >> 2, t4 = lane & 3;
    const int b = blockIdx.x >> 4, n = blockIdx.x & 15;
    const int crow = tid >> 3, cseg = tid & 7;   // cp.async mapping

    if (tid == 0) misc[0] = 0;
    __syncthreads();

    // ---- mask compaction ----
    const int* mbase = d_mask + (b*NWAY + n) * LD;
    {
        int mk = mbase[tid];
        unsigned bits = __ballot_sync(0xffffffffu, mk);
        if (lane == 0) misc[2 + w] = atomicAdd(&misc[0], __popc(bits));
        __syncwarp();
        int pos = misc[2 + w] + __popc(bits & ((1u << lane) - 1u));
        if (mk) sidx[pos] = tid;
    }

    // ---- q normalize + fp16 hi/lo -> smem (own warp rows), then B frags -> regs ----
    {
        const float* qb = q_reps + (size_t)b * LQ * D_;
        #pragma unroll
        for (int i = 0; i < 8; i++){
            int r = w*8 + i;
            float4 v = ((const float4*)(qb + (size_t)r * D_))[lane];
            float ss = v.x*v.x + v.y*v.y + v.z*v.z + v.w*v.w;
            #pragma unroll
            for (int o = 16; o; o >>= 1) ss += __shfl_xor_sync(0xffffffffu, ss, o);
            float inv = 1.0f / fmaxf(sqrtf(ss), EPSN);
            float x0 = v.x*inv, x1 = v.y*inv, x2 = v.z*inv, x3 = v.w*inv;
            __half h0 = __float2half_rn(x0), h1 = __float2half_rn(x1);
            __half h2 = __float2half_rn(x2), h3 = __float2half_rn(x3);
            float l0 = x0 - __half2float(h0), l1 = x1 - __half2float(h1);
            float l2 = x2 - __half2float(h2), l3 = x3 - __half2float(h3);
            *(uint2*)(qhi + r*SP + 2*lane) = make_uint2(pkh(h0,h1), pkh(h2,h3));
            *(uint2*)(qlo + r*SP + 2*lane) =
                make_uint2(pkh(__float2half_rn(l0), __float2half_rn(l1)),
                           pkh(__float2half_rn(l2), __float2half_rn(l3)));
        }
    }
    __syncwarp();
    uint32_t Bh0[8], Bh1[8], Bl0[8], Bl1[8];
    {
        int qr = (w*8 + g)*SP;
        #pragma unroll
        for (int ks = 0; ks < 8; ks++){
            Bh0[ks] = qhi[qr + ks*8 + t4];  Bh1[ks] = qhi[qr + ks*8 + t4 + 4];
            Bl0[ks] = qlo[qr + ks*8 + t4];  Bl1[ks] = qlo[qr + ks*8 + t4 + 4];
        }
    }
    __syncthreads();   // sidx ready, all q reads done -> W_U reusable as fp32 stage

    const int M_act = misc[0];
    const int nchunk = (M_act + 31) >> 5;
    const float* dbase = d_reps + (size_t)(b*NWAY + n) * LD * D_;

    // ---- prefetch chunks 0,1 ----
    #pragma unroll
    for (int c0 = 0; c0 < 2; c0++){
        if (c0 < nchunk){
            int j = c0*32 + crow;
            int orig = sidx[(j < M_act) ? j : 0];
            const char* src = (const char*)(dbase + (size_t)orig * D_);
            uint32_t dst = smem32 + (uint32_t)((W_F32 + (c0&1)*4096 + crow*128)*4);
            #pragma unroll
            for (int it = 0; it < 4; it++){
                uint32_t o = (uint32_t)((cseg + 8*it) * 16);
                asm volatile("cp.async.cg.shared.global [%0], [%1], 16;"
                             :: "r"(dst + o), "l"(src + o) : "memory");
            }
        }
        asm volatile("cp.async.commit_group;" ::: "memory");
    }

    float cm0 = NEGV, cm1 = NEGV;
    const uint32_t afragoff = (uint32_t)((lane & 15)*SP*4 + (lane >> 4)*16);

    for (int c = 0; c < nchunk; c++){
        const int slot = c & 1;
        asm volatile("cp.async.wait_group 1;" ::: "memory");
        __syncthreads();

        // ---- convert 4 rows per warp: fp32 smem -> fp16 A tile + norms ----
        {
            const float* fb = (const float*)(sm + W_F32 + slot*4096);
            unsigned* ab = sm + W_A16 + slot*2176;
            #pragma unroll
            for (int i = 0; i < 4; i++){
                int row = w*4 + i;
                float4 v = *(const float4*)(fb + row*128 + lane*4);
                float ss = v.x*v.x + v.y*v.y + v.z*v.z + v.w*v.w;
                #pragma unroll
                for (int o = 16; o; o >>= 1) ss += __shfl_xor_sync(0xffffffffu, ss, o);
                *(uint2*)(ab + row*SP + 2*lane) =
                    make_uint2(pkh(__float2half_rn(v.x), __float2half_rn(v.y)),
                               pkh(__float2half_rn(v.z), __float2half_rn(v.w)));
                if (lane == 0){
                    bool val = (c*32 + row) < M_act;
                    ssc[slot*32 + row] = val ? 1.0f / fmaxf(sqrtf(ss), EPSN) : 0.0f;
                    sof[slot*32 + row] = val ? 0.0f : NEGV;
                }
            }
        }
        __syncthreads();

        // ---- prefetch chunk c+2 into the buffer just freed ----
        if (c + 2 < nchunk){
            int j = (c+2)*32 + crow;
            int orig = sidx[(j < M_act) ? j : 0];
            const char* src = (const char*)(dbase + (size_t)orig * D_);
            uint32_t dst = smem32 + (uint32_t)((W_F32 + slot*4096 + crow*128)*4);
            #pragma unroll
            for (int it = 0; it < 4; it++){
                uint32_t o = (uint32_t)((cseg + 8*it) * 16);
                asm volatile("cp.async.cg.shared.global [%0], [%1], 16;"
                             :: "r"(dst + o), "l"(src + o) : "memory");
            }
        }
        asm volatile("cp.async.commit_group;" ::: "memory");

        // ---- MMA: each warp does its n8 tile over both m16 tiles ----
        const uint32_t abB = smem32 + (uint32_t)((W_A16 + slot*2176)*4) + afragoff;
        #pragma unroll
        for (int mt = 0; mt < 2; mt++){
            float C[4] = {0.f, 0.f, 0.f, 0.f};
            #pragma unroll
            for (int ks = 0; ks < 8; ks++){
                uint32_t a0, a1, a2, a3;
                ldmx4(a0, a1, a2, a3, abB + (uint32_t)(mt*16*SP*4 + ks*32));
                mma16816(C, a0, a1, a2, a3, Bh0[ks], Bh1[ks]);
                mma16816(C, a0, a1, a2, a3, Bl0[ks], Bl1[ks]);
            }
            float s0 = ssc[slot*32 + mt*16 + g],     o0 = sof[slot*32 + mt*16 + g];
            float s1 = ssc[slot*32 + mt*16 + g + 8], o1 = sof[slot*32 + mt*16 + g + 8];
            cm0 = fmaxf(cm0, fmaf(C[0], s0, o0));
            cm1 = fmaxf(cm1, fmaf(C[1], s0, o0));
            cm0 = fmaxf(cm0, fmaf(C[2], s1, o1));
            cm1 = fmaxf(cm1, fmaf(C[3], s1, o1));
        }
    }

    // ---- reduce: max over g (rows), then sum the warp's 8 q columns ----
    #pragma unroll
    for (int o = 4; o < 32; o <<= 1){
        cm0 = fmaxf(cm0, __shfl_xor_sync(0xffffffffu, cm0, o));
        cm1 = fmaxf(cm1, __shfl_xor_sync(0xffffffffu, cm1, o));
    }
    float s = cm0 + cm1;
    s += __shfl_xor_sync(0xffffffffu, s, 1);
    s += __shfl_xor_sync(0xffffffffu, s, 2);
    if (lane == 0) ws[w] = s;
    __syncthreads();
    if (tid == 0){
        float sc = 0.f;
        #pragma unroll
        for (int i = 0; i < 8; i++) sc += ws[i];
        g_scores[b*NWAY + n] = sc;
    }
    __syncthreads();

    // ---- last CTA computes the KL loss ----
    if (tid == 0){
        __threadfence();
        int dcount = atomicAdd(&g_done, 1);
        misc[1] = (dcount == (int)gridDim.x - 1) ? 1 : 0;
    }
    __syncthreads();
    if (misc[1]){
        __threadfence();
        #pragma unroll
        for (int rep = 0; rep < 2; rep++){
            int bb = rep*16 + (tid >> 4);
            int nn = tid & 15;
            float sv  = g_scores[bb*NWAY + nn];
            float lab = labels[bb*NWAY + nn];
            float mx = sv;
            #pragma unroll
            for (int o = 1; o < 16; o <<= 1) mx = fmaxf(mx, __shfl_xor_sync(0xffffffffu, mx, o));
            float e = expf(sv - mx);
            float se = e;
            #pragma unroll
            for (int o = 1; o < 16; o <<= 1) se += __shfl_xor_sync(0xffffffffu, se, o);
            float lse = mx + logf(se);
            float t = expf(lab) * (lab - (sv - lse));
            #pragma unroll
            for (int o = 1; o < 16; o <<= 1) t += __shfl_xor_sync(0xffffffffu, t, o);
            if ((lane & 15) == 0) lpart[rep*16 + (tid >> 4)] = t;
        }
        __syncthreads();
        if (tid < 32){
            float v = lpart[tid];
            #pragma unroll
            for (int o = 16; o; o >>= 1) v += __shfl_xor_sync(0xffffffffu, v, o);
            if (tid == 0){
                out[0] = v / (float)B_;
                __threadfence();
                g_done = 0;
            }
        }
    }
}

extern "C" void kernel_launch(void* const* d_in, const int* in_sizes, int n_in,
                              void* d_out, int out_size){
    const float* q_reps = (const float*)d_in[0];
    const float* d_reps = (const float*)d_in[1];
    const int*   d_mask = (const int*)  d_in[2];
    const float* labels = (const float*)d_in[3];

    cudaFuncSetAttribute(k_fused, cudaFuncAttributeMaxDynamicSharedMemorySize, SMEM_BYTES);
    k_fused<<<B_*NWAY, 256, SMEM_BYTES>>>(q_reps, d_reps, d_mask, labels, (float*)d_out);
}